// round 7
// baseline (speedup 1.0000x reference)
#include <cuda_runtime.h>
#include <cuda_bf16.h>
#include <math.h>

typedef unsigned int u32;

#define H 4096
#define IDIM 5632
#define NE 8
#define T 4096
#define NSLOTS (T * 2)
#define BM 128
#define BN 128
#define BK 32
#define SMEMSZ (1024 + 2 * 32768)

// ---------------- scratch (device globals; allocation-free) ----------------
__device__ float g_tmp[(size_t)NSLOTS * IDIM];   // raw gate values
__device__ float g_act[(size_t)NSLOTS * IDIM];   // silu(g)*u
__device__ int   g_counts[NE];
__device__ int   g_offsets[NE];
__device__ int   g_cursor[NE];
__device__ int   g_topi[T * 2];
__device__ float g_topw[T * 2];
__device__ int   g_tok[NSLOTS];
__device__ float g_sw[NSLOTS];
__device__ float g_psum[NE];
__device__ float g_zsum;

// ---------------- helpers ----------------
__device__ __forceinline__ u32 smem_u32(const void* p) {
    u32 a;
    asm("{ .reg .u64 t; cvta.to.shared.u64 t, %1; cvt.u32.u64 %0, t; }" : "=r"(a) : "l"(p));
    return a;
}
// row-major bf16 tile [128][32], 64B rows of 4 16B chunks, XOR swizzle
__device__ __forceinline__ u32 swoff(int row, int ch) {
    return (u32)(row * 64 + ((ch ^ ((row >> 1) & 3)) << 4));
}
__device__ __forceinline__ u32 prmt_hi(float a, float b) {  // low=bf16(a) trunc, high=bf16(b)
    u32 r;
    asm("prmt.b32 %0, %1, %2, 0x7632;" : "=r"(r) : "r"(__float_as_uint(a)), "r"(__float_as_uint(b)));
    return r;
}
__device__ __forceinline__ float resid(float a) {
    return a - __uint_as_float(__float_as_uint(a) & 0xFFFF0000u);
}
__device__ __forceinline__ u32 pack_lo(float a, float b) {  // low=bf16rn(a), high=bf16rn(b)
    u32 r;
    asm("cvt.rn.bf16x2.f32 %0, %1, %2;" : "=r"(r) : "f"(b), "f"(a));
    return r;
}
__device__ __forceinline__ void sts8(u32 hi_a, u32 lo_a, float4 v0, float4 v1) {
    u32 h0 = prmt_hi(v0.x, v0.y), h1 = prmt_hi(v0.z, v0.w);
    u32 h2 = prmt_hi(v1.x, v1.y), h3 = prmt_hi(v1.z, v1.w);
    u32 l0 = pack_lo(resid(v0.x), resid(v0.y)), l1 = pack_lo(resid(v0.z), resid(v0.w));
    u32 l2 = pack_lo(resid(v1.x), resid(v1.y)), l3 = pack_lo(resid(v1.z), resid(v1.w));
    asm volatile("st.shared.v4.b32 [%0], {%1,%2,%3,%4};" :: "r"(hi_a), "r"(h0), "r"(h1), "r"(h2), "r"(h3) : "memory");
    asm volatile("st.shared.v4.b32 [%0], {%1,%2,%3,%4};" :: "r"(lo_a), "r"(l0), "r"(l1), "r"(l2), "r"(l3) : "memory");
}
#define LDSM4(R, A)                                                             \
    asm volatile("ldmatrix.sync.aligned.m8n8.x4.shared.b16 {%0,%1,%2,%3}, [%4];" \
        : "=r"((R)[0]), "=r"((R)[1]), "=r"((R)[2]), "=r"((R)[3]) : "r"(A))

__device__ __forceinline__ void mma16816(float* d, const u32* a, const u32* b) {
    asm volatile(
        "mma.sync.aligned.m16n8k16.row.col.f32.bf16.bf16.f32 "
        "{%0,%1,%2,%3},{%4,%5,%6,%7},{%8,%9},{%0,%1,%2,%3};"
        : "+f"(d[0]), "+f"(d[1]), "+f"(d[2]), "+f"(d[3])
        : "r"(a[0]), "r"(a[1]), "r"(a[2]), "r"(a[3]), "r"(b[0]), "r"(b[1]));
}

// ---------------- small kernels ----------------
__global__ void reset_kernel() {
    int i = threadIdx.x;
    if (i < NE) { g_counts[i] = 0; g_cursor[i] = 0; g_psum[i] = 0.f; }
    if (i == 0) g_zsum = 0.f;
}

__global__ void router_kernel(const float* __restrict__ x,
                              const float* __restrict__ Wgate) {
    int t = blockIdx.x;
    const float* xr = x + (size_t)t * H;
    float p[NE];
#pragma unroll
    for (int e = 0; e < NE; ++e) p[e] = 0.f;
    for (int c = threadIdx.x; c < H; c += blockDim.x) {
        float xv = xr[c];
#pragma unroll
        for (int e = 0; e < NE; ++e) p[e] += xv * Wgate[e * H + c];
    }
    __shared__ float sm[NE][128];
#pragma unroll
    for (int e = 0; e < NE; ++e) sm[e][threadIdx.x] = p[e];
    __syncthreads();
    for (int s = 64; s > 0; s >>= 1) {
        if (threadIdx.x < s)
#pragma unroll
            for (int e = 0; e < NE; ++e)
                sm[e][threadIdx.x] += sm[e][threadIdx.x + s];
        __syncthreads();
    }
    if (threadIdx.x == 0) {
        float lg[NE];
#pragma unroll
        for (int e = 0; e < NE; ++e) lg[e] = sm[e][0];
        float mx = lg[0];
#pragma unroll
        for (int e = 1; e < NE; ++e) mx = fmaxf(mx, lg[e]);
        float se = 0.f, pr[NE];
#pragma unroll
        for (int e = 0; e < NE; ++e) { pr[e] = expf(lg[e] - mx); se += pr[e]; }
        float inv = 1.f / se;
#pragma unroll
        for (int e = 0; e < NE; ++e) pr[e] *= inv;
        int i0 = 0;
#pragma unroll
        for (int e = 1; e < NE; ++e) if (pr[e] > pr[i0]) i0 = e;
        int i1 = (i0 == 0) ? 1 : 0;
#pragma unroll
        for (int e = 0; e < NE; ++e)
            if (e != i0 && pr[e] > pr[i1]) i1 = e;
        float w0 = pr[i0], w1 = pr[i1];
        float ws = 1.f / (w0 + w1);
        g_topi[2 * t] = i0;     g_topw[2 * t] = w0 * ws;
        g_topi[2 * t + 1] = i1; g_topw[2 * t + 1] = w1 * ws;
        atomicAdd(&g_counts[i0], 1);
        atomicAdd(&g_counts[i1], 1);
#pragma unroll
        for (int e = 0; e < NE; ++e) atomicAdd(&g_psum[e], pr[e]);
        float lse = mx + logf(se);
        atomicAdd(&g_zsum, lse * lse);
    }
}

__global__ void finalize_kernel(float* __restrict__ out, int out_size) {
    if (threadIdx.x == 0 && blockIdx.x == 0) {
        int off = 0;
        for (int e = 0; e < NE; ++e) { g_offsets[e] = off; g_cursor[e] = off; off += g_counts[e]; }
        float aux = 0.f;
        for (int e = 0; e < NE; ++e)
            aux += (g_psum[e] / (float)T) * ((float)g_counts[e] / (float)(T * 2));
        aux *= (float)NE;
        float z = g_zsum / (float)T;
        if (out_size > T * H) out[(size_t)T * H] = 0.02f * aux + 0.001f * z;
    }
}

__global__ void assign_kernel() {
    int t = blockIdx.x * blockDim.x + threadIdx.x;
    if (t >= T) return;
#pragma unroll
    for (int k = 0; k < 2; ++k) {
        int e = g_topi[2 * t + k];
        int s = atomicAdd(&g_cursor[e], 1);
        g_tok[s] = t;
        g_sw[s] = g_topw[2 * t + k];
    }
}

// ---------------- unified split-bf16 MMA GEMM ----------------
// MODE 0: A=x(gather), B=Wg  -> g_tmp (raw gate)
// MODE 1: A=x(gather), B=Wu  -> g_act = silu(g_tmp)*u
// MODE 2: A=g_act,     B=Wd  -> out[tok] += w * result (atomic)
template <int MODE>
__global__ __launch_bounds__(256)
void gemm_kernel(const float* __restrict__ Asrc, const float* __restrict__ W,
                 float* __restrict__ outp) {
    constexpr int KD = (MODE == 2) ? IDIM : H;
    constexpr int KT = KD / BK;

    int e = blockIdx.z;
    int cnt = g_counts[e];
    int m0 = blockIdx.x * BM;
    if (m0 >= cnt) return;
    int base = g_offsets[e];
    int n0 = blockIdx.y * BN;

    extern __shared__ char smem[];
    const float** aptr = (const float**)smem;   // 128 row pointers (1 KB)
    u32 tiles = smem_u32(smem) + 1024;          // 2 stages x 32 KB

    int tid = threadIdx.x, lane = tid & 31, wid = tid >> 5;
    int wm = wid & 3, wn = wid >> 2;

    if (tid < 128) {
        int r = m0 + tid;
        int slot = base + ((r < cnt) ? r : (cnt - 1));
        aptr[tid] = (MODE == 2) ? (g_act + (size_t)slot * IDIM)
                                : (Asrc + (size_t)g_tok[slot] * H);
    }
    __syncthreads();

    const float* wB = W + (size_t)e * ((size_t)IDIM * H) + (size_t)n0 * KD;

    int lr = tid >> 1;           // loader row 0..127
    int lc = (tid & 1) * 2;      // chunk base (chunk = 8 elems)
    const float* aRow = aptr[lr] + lc * 8;
    const float* bRow = wB + (size_t)lr * KD + lc * 8;
    u32 sA0 = swoff(lr, lc), sA1 = swoff(lr, lc + 1);

    // precompute ldmatrix addresses (stage-relative)
    u32 aOff[2], bOff[4];
#pragma unroll
    for (int mi = 0; mi < 2; ++mi) {
        int row = wm * 32 + mi * 16 + (lane & 15);
        aOff[mi] = swoff(row, lane >> 4);
    }
#pragma unroll
    for (int p = 0; p < 4; ++p) {
        int row = wn * 64 + p * 16 + ((lane >> 4) << 3) + (lane & 7);
        bOff[p] = swoff(row, (lane >> 3) & 1);
    }

    // preload stage 0
    {
        float4 a0 = *(const float4*)(aRow);
        float4 a1 = *(const float4*)(aRow + 4);
        float4 a2 = *(const float4*)(aRow + 8);
        float4 a3 = *(const float4*)(aRow + 12);
        float4 b0 = *(const float4*)(bRow);
        float4 b1 = *(const float4*)(bRow + 4);
        float4 b2 = *(const float4*)(bRow + 8);
        float4 b3 = *(const float4*)(bRow + 12);
        sts8(tiles + sA0, tiles + 8192 + sA0, a0, a1);
        sts8(tiles + sA1, tiles + 8192 + sA1, a2, a3);
        sts8(tiles + 16384 + sA0, tiles + 24576 + sA0, b0, b1);
        sts8(tiles + 16384 + sA1, tiles + 24576 + sA1, b2, b3);
    }
    __syncthreads();

    float acc[2][8][4];
#pragma unroll
    for (int i = 0; i < 2; ++i)
#pragma unroll
        for (int j = 0; j < 8; ++j)
#pragma unroll
            for (int c = 0; c < 4; ++c) acc[i][j][c] = 0.f;

#pragma unroll 1
    for (int kt = 0; kt < KT; ++kt) {
        int b = kt & 1;
        u32 stage = tiles + b * 32768;
        u32 ns = tiles + (b ^ 1) * 32768;

        // prefetch next-k LDGs (latency hidden under ks=0 MMA block)
        float4 pa0, pa1, pa2, pa3, pb0, pb1, pb2, pb3;
        bool pf = (kt + 1 < KT);
        if (pf) {
            int k0 = (kt + 1) * BK;
            pa0 = *(const float4*)(aRow + k0);
            pa1 = *(const float4*)(aRow + k0 + 4);
            pa2 = *(const float4*)(aRow + k0 + 8);
            pa3 = *(const float4*)(aRow + k0 + 12);
            pb0 = *(const float4*)(bRow + k0);
            pb1 = *(const float4*)(bRow + k0 + 4);
            pb2 = *(const float4*)(bRow + k0 + 8);
            pb3 = *(const float4*)(bRow + k0 + 12);
        }

#pragma unroll
        for (int ks = 0; ks < 2; ++ks) {
            u32 ko = (u32)(ks * 32);  // 2 chunks = 32B offset pre-swizzle on ch axis
            // --- load ALL fragments for this ks first ---
            u32 Ah[2][4], Al[2][4], Bh[4][4], Bl[4][4];
#pragma unroll
            for (int mi = 0; mi < 2; ++mi) {
                u32 off = aOff[mi] ^ ko;   // ch bits live in bits [4:5] of chunk index*16
                LDSM4(Ah[mi], stage + off);
                LDSM4(Al[mi], stage + 8192 + off);
            }
#pragma unroll
            for (int p = 0; p < 4; ++p) {
                u32 off = bOff[p] ^ ko;
                LDSM4(Bh[p], stage + 16384 + off);
                LDSM4(Bl[p], stage + 24576 + off);
            }
            // --- term-major MMA issue: dependent-acc distance = 16 ---
#pragma unroll
            for (int p = 0; p < 4; ++p)
#pragma unroll
                for (int mi = 0; mi < 2; ++mi) {
                    mma16816(acc[mi][2 * p],     Ah[mi], Bh[p]);
                    mma16816(acc[mi][2 * p + 1], Ah[mi], Bh[p] + 2);
                }
#pragma unroll
            for (int p = 0; p < 4; ++p)
#pragma unroll
                for (int mi = 0; mi < 2; ++mi) {
                    mma16816(acc[mi][2 * p],     Ah[mi], Bl[p]);
                    mma16816(acc[mi][2 * p + 1], Ah[mi], Bl[p] + 2);
                }
#pragma unroll
            for (int p = 0; p < 4; ++p)
#pragma unroll
                for (int mi = 0; mi < 2; ++mi) {
                    mma16816(acc[mi][2 * p],     Al[mi], Bh[p]);
                    mma16816(acc[mi][2 * p + 1], Al[mi], Bh[p] + 2);
                }
            // interleave next-stage STS between the two ks halves
            if (ks == 0 && pf) {
                sts8(ns + sA0, ns + 8192 + sA0, pa0, pa1);
                sts8(ns + sA1, ns + 8192 + sA1, pa2, pa3);
                sts8(ns + 16384 + sA0, ns + 24576 + sA0, pb0, pb1);
                sts8(ns + 16384 + sA1, ns + 24576 + sA1, pb2, pb3);
            }
        }
        __syncthreads();
    }

    // NOTE on ko XOR: chunk index ch occupies bits [4:5] of the byte offset
    // (16B chunks), swizzle XORs bits[4:5] with row bits — adding ks*2 to ch
    // pre-swizzle equals XORing (ks*2)<<4 = ks*32 post-swizzle since base ch
    // for A is (lane>>4) in {0,1} and ks*2 flips only bit 5; for B base ch is
    // ((lane>>3)&1) in {0,1}, same argument.

    // epilogue
    int rA = m0 + wm * 32 + (lane >> 2);
    int cA = n0 + wn * 64 + (lane & 3) * 2;
#pragma unroll
    for (int mi = 0; mi < 2; ++mi) {
#pragma unroll
        for (int ni = 0; ni < 8; ++ni) {
            int col = cA + ni * 8;
#pragma unroll
            for (int h = 0; h < 2; ++h) {
                int r = rA + mi * 16 + h * 8;
                if (r >= cnt) continue;
                float v0 = acc[mi][ni][2 * h], v1 = acc[mi][ni][2 * h + 1];
                int slot = base + r;
                if (MODE == 0) {
                    float2 o; o.x = v0; o.y = v1;
                    *(float2*)(g_tmp + (size_t)slot * IDIM + col) = o;
                } else if (MODE == 1) {
                    float2 g = *(const float2*)(g_tmp + (size_t)slot * IDIM + col);
                    float2 o;
                    o.x = g.x / (1.f + __expf(-g.x)) * v0;
                    o.y = g.y / (1.f + __expf(-g.y)) * v1;
                    *(float2*)(g_act + (size_t)slot * IDIM + col) = o;
                } else {
                    float w = g_sw[slot];
                    float* d = outp + (size_t)g_tok[slot] * H + col;
                    atomicAdd(d, w * v0);
                    atomicAdd(d + 1, w * v1);
                }
            }
        }
    }
}

// ---------------- launch ----------------
extern "C" void kernel_launch(void* const* d_in, const int* in_sizes, int n_in,
                              void* d_out, int out_size) {
    const float* x     = (const float*)d_in[0];
    const float* Wgate = (const float*)d_in[1];
    const float* Wg    = (const float*)d_in[2];
    const float* Wu    = (const float*)d_in[3];
    const float* Wd    = (const float*)d_in[4];
    float* out = (float*)d_out;

    cudaFuncSetAttribute(gemm_kernel<0>, cudaFuncAttributeMaxDynamicSharedMemorySize, SMEMSZ);
    cudaFuncSetAttribute(gemm_kernel<1>, cudaFuncAttributeMaxDynamicSharedMemorySize, SMEMSZ);
    cudaFuncSetAttribute(gemm_kernel<2>, cudaFuncAttributeMaxDynamicSharedMemorySize, SMEMSZ);

    cudaMemsetAsync(out, 0, (size_t)out_size * sizeof(float));
    reset_kernel<<<1, 32>>>();
    router_kernel<<<T, 128>>>(x, Wgate);
    finalize_kernel<<<1, 32>>>(out, out_size);
    assign_kernel<<<(T + 255) / 256, 256>>>();

    dim3 g1(T / BM, IDIM / BN, NE);   // (32, 44, 8)
    gemm_kernel<0><<<g1, 256, SMEMSZ>>>(x, Wg, out);
    gemm_kernel<1><<<g1, 256, SMEMSZ>>>(x, Wu, out);

    dim3 g2(T / BM, H / BN, NE);      // (32, 32, 8)
    gemm_kernel<2><<<g2, 256, SMEMSZ>>>(x, Wd, out);
}

// round 8
// speedup vs baseline: 1.4757x; 1.4757x over previous
#include <cuda_runtime.h>
#include <cuda_fp16.h>
#include <math.h>

typedef unsigned int u32;

#define H 4096
#define IDIM 5632
#define NE 8
#define T 4096
#define NSLOTS (T * 2)
#define BM 128
#define BN 128
#define BK 32
// stage: A(hi) 8KB @0 | Bh 8KB @8192 | Bl 8KB @16384  => 24KB; 2 stages
#define STAGE 24576
#define SMEMSZ (1024 + 2 * STAGE)

// ---------------- scratch (device globals; allocation-free) ----------------
__device__ float g_tmp[(size_t)NSLOTS * IDIM];   // raw gate values
__device__ float g_act[(size_t)NSLOTS * IDIM];   // silu(g)*u
__device__ int   g_counts[NE];
__device__ int   g_offsets[NE];
__device__ int   g_cursor[NE];
__device__ int   g_topi[T * 2];
__device__ float g_topw[T * 2];
__device__ int   g_tok[NSLOTS];
__device__ float g_sw[NSLOTS];
__device__ float g_psum[NE];
__device__ float g_zsum;

// ---------------- helpers ----------------
__device__ __forceinline__ u32 smem_u32(const void* p) {
    u32 a;
    asm("{ .reg .u64 t; cvta.to.shared.u64 t, %1; cvt.u32.u64 %0, t; }" : "=r"(a) : "l"(p));
    return a;
}
// row-major fp16 tile [128][32], 64B rows of 4 16B chunks, XOR swizzle
__device__ __forceinline__ u32 swoff(int row, int ch) {
    return (u32)(row * 64 + ((ch ^ ((row >> 1) & 3)) << 4));
}
__device__ __forceinline__ u32 packh(float lo, float hi) {  // low=f16rn(lo), high=f16rn(hi)
    u32 r;
    asm("cvt.rn.f16x2.f32 %0, %1, %2;" : "=r"(r) : "f"(hi), "f"(lo));
    return r;
}
__device__ __forceinline__ float h2f_rn(float a) {          // fp32 -> fp16 -> fp32
    float r;
    asm("{ .reg .f16 t; cvt.rn.f16.f32 t, %1; cvt.f32.f16 %0, t; }" : "=f"(r) : "f"(a));
    return r;
}
// store 8 fp16 (hi only) for A
__device__ __forceinline__ void sts_a(u32 addr, float4 v0, float4 v1) {
    u32 h0 = packh(v0.x, v0.y), h1 = packh(v0.z, v0.w);
    u32 h2 = packh(v1.x, v1.y), h3 = packh(v1.z, v1.w);
    asm volatile("st.shared.v4.b32 [%0], {%1,%2,%3,%4};" :: "r"(addr), "r"(h0), "r"(h1), "r"(h2), "r"(h3) : "memory");
}
// store 8 fp16 hi + 8 fp16 lo (residual) for B
__device__ __forceinline__ void sts_b(u32 hi_a, u32 lo_a, float4 v0, float4 v1) {
    u32 h0 = packh(v0.x, v0.y), h1 = packh(v0.z, v0.w);
    u32 h2 = packh(v1.x, v1.y), h3 = packh(v1.z, v1.w);
    u32 l0 = packh(v0.x - h2f_rn(v0.x), v0.y - h2f_rn(v0.y));
    u32 l1 = packh(v0.z - h2f_rn(v0.z), v0.w - h2f_rn(v0.w));
    u32 l2 = packh(v1.x - h2f_rn(v1.x), v1.y - h2f_rn(v1.y));
    u32 l3 = packh(v1.z - h2f_rn(v1.z), v1.w - h2f_rn(v1.w));
    asm volatile("st.shared.v4.b32 [%0], {%1,%2,%3,%4};" :: "r"(hi_a), "r"(h0), "r"(h1), "r"(h2), "r"(h3) : "memory");
    asm volatile("st.shared.v4.b32 [%0], {%1,%2,%3,%4};" :: "r"(lo_a), "r"(l0), "r"(l1), "r"(l2), "r"(l3) : "memory");
}
#define LDSM4(R, A)                                                             \
    asm volatile("ldmatrix.sync.aligned.m8n8.x4.shared.b16 {%0,%1,%2,%3}, [%4];" \
        : "=r"((R)[0]), "=r"((R)[1]), "=r"((R)[2]), "=r"((R)[3]) : "r"(A))

__device__ __forceinline__ void mma16816(float* d, const u32* a, const u32* b) {
    asm volatile(
        "mma.sync.aligned.m16n8k16.row.col.f32.f16.f16.f32 "
        "{%0,%1,%2,%3},{%4,%5,%6,%7},{%8,%9},{%0,%1,%2,%3};"
        : "+f"(d[0]), "+f"(d[1]), "+f"(d[2]), "+f"(d[3])
        : "r"(a[0]), "r"(a[1]), "r"(a[2]), "r"(a[3]), "r"(b[0]), "r"(b[1]));
}

// ---------------- small kernels ----------------
__global__ void reset_kernel() {
    int i = threadIdx.x;
    if (i < NE) { g_counts[i] = 0; g_cursor[i] = 0; g_psum[i] = 0.f; }
    if (i == 0) g_zsum = 0.f;
}

__global__ void router_kernel(const float* __restrict__ x,
                              const float* __restrict__ Wgate) {
    int t = blockIdx.x;
    const float* xr = x + (size_t)t * H;
    float p[NE];
#pragma unroll
    for (int e = 0; e < NE; ++e) p[e] = 0.f;
    for (int c = threadIdx.x; c < H; c += blockDim.x) {
        float xv = xr[c];
#pragma unroll
        for (int e = 0; e < NE; ++e) p[e] += xv * Wgate[e * H + c];
    }
    __shared__ float sm[NE][128];
#pragma unroll
    for (int e = 0; e < NE; ++e) sm[e][threadIdx.x] = p[e];
    __syncthreads();
    for (int s = 64; s > 0; s >>= 1) {
        if (threadIdx.x < s)
#pragma unroll
            for (int e = 0; e < NE; ++e)
                sm[e][threadIdx.x] += sm[e][threadIdx.x + s];
        __syncthreads();
    }
    if (threadIdx.x == 0) {
        float lg[NE];
#pragma unroll
        for (int e = 0; e < NE; ++e) lg[e] = sm[e][0];
        float mx = lg[0];
#pragma unroll
        for (int e = 1; e < NE; ++e) mx = fmaxf(mx, lg[e]);
        float se = 0.f, pr[NE];
#pragma unroll
        for (int e = 0; e < NE; ++e) { pr[e] = expf(lg[e] - mx); se += pr[e]; }
        float inv = 1.f / se;
#pragma unroll
        for (int e = 0; e < NE; ++e) pr[e] *= inv;
        int i0 = 0;
#pragma unroll
        for (int e = 1; e < NE; ++e) if (pr[e] > pr[i0]) i0 = e;
        int i1 = (i0 == 0) ? 1 : 0;
#pragma unroll
        for (int e = 0; e < NE; ++e)
            if (e != i0 && pr[e] > pr[i1]) i1 = e;
        float w0 = pr[i0], w1 = pr[i1];
        float ws = 1.f / (w0 + w1);
        g_topi[2 * t] = i0;     g_topw[2 * t] = w0 * ws;
        g_topi[2 * t + 1] = i1; g_topw[2 * t + 1] = w1 * ws;
        atomicAdd(&g_counts[i0], 1);
        atomicAdd(&g_counts[i1], 1);
#pragma unroll
        for (int e = 0; e < NE; ++e) atomicAdd(&g_psum[e], pr[e]);
        float lse = mx + logf(se);
        atomicAdd(&g_zsum, lse * lse);
    }
}

__global__ void finalize_kernel(float* __restrict__ out, int out_size) {
    if (threadIdx.x == 0 && blockIdx.x == 0) {
        int off = 0;
        for (int e = 0; e < NE; ++e) { g_offsets[e] = off; g_cursor[e] = off; off += g_counts[e]; }
        float aux = 0.f;
        for (int e = 0; e < NE; ++e)
            aux += (g_psum[e] / (float)T) * ((float)g_counts[e] / (float)(T * 2));
        aux *= (float)NE;
        float z = g_zsum / (float)T;
        if (out_size > T * H) out[(size_t)T * H] = 0.02f * aux + 0.001f * z;
    }
}

__global__ void assign_kernel() {
    int t = blockIdx.x * blockDim.x + threadIdx.x;
    if (t >= T) return;
#pragma unroll
    for (int k = 0; k < 2; ++k) {
        int e = g_topi[2 * t + k];
        int s = atomicAdd(&g_cursor[e], 1);
        g_tok[s] = t;
        g_sw[s] = g_topw[2 * t + k];
    }
}

// ---------------- unified fp16 2-term MMA GEMM ----------------
// D = Ah * (Bh + Bl);  A single fp16, B split hi+lo.
// MODE 0: A=x(gather), B=Wg  -> g_tmp (raw gate)
// MODE 1: A=x(gather), B=Wu  -> g_act = silu(g_tmp)*u
// MODE 2: A=g_act,     B=Wd  -> out[tok] += w * result (atomic)
template <int MODE>
__global__ __launch_bounds__(256)
void gemm_kernel(const float* __restrict__ Asrc, const float* __restrict__ W,
                 float* __restrict__ outp) {
    constexpr int KD = (MODE == 2) ? IDIM : H;
    constexpr int KT = KD / BK;

    int e = blockIdx.z;
    int cnt = g_counts[e];
    int m0 = blockIdx.x * BM;
    if (m0 >= cnt) return;
    int base = g_offsets[e];
    int n0 = blockIdx.y * BN;

    extern __shared__ char smem[];
    const float** aptr = (const float**)smem;   // 128 row pointers (1 KB)
    u32 tiles = smem_u32(smem) + 1024;          // 2 stages x 24 KB

    int tid = threadIdx.x, lane = tid & 31, wid = tid >> 5;
    int wm = wid & 3, wn = wid >> 2;

    if (tid < 128) {
        int r = m0 + tid;
        int slot = base + ((r < cnt) ? r : (cnt - 1));
        aptr[tid] = (MODE == 2) ? (g_act + (size_t)slot * IDIM)
                                : (Asrc + (size_t)g_tok[slot] * H);
    }
    __syncthreads();

    const float* wB = W + (size_t)e * ((size_t)IDIM * H) + (size_t)n0 * KD;

    int lr = tid >> 1;           // loader row 0..127
    int lc = (tid & 1) * 2;      // chunk base (chunk = 8 fp16 = 16B)
    const float* aRow = aptr[lr] + lc * 8;
    const float* bRow = wB + (size_t)lr * KD + lc * 8;
    u32 sA0 = swoff(lr, lc), sA1 = swoff(lr, lc + 1);

    // preload stage 0
    {
        float4 a0 = *(const float4*)(aRow);
        float4 a1 = *(const float4*)(aRow + 4);
        float4 a2 = *(const float4*)(aRow + 8);
        float4 a3 = *(const float4*)(aRow + 12);
        float4 b0 = *(const float4*)(bRow);
        float4 b1 = *(const float4*)(bRow + 4);
        float4 b2 = *(const float4*)(bRow + 8);
        float4 b3 = *(const float4*)(bRow + 12);
        sts_a(tiles + sA0, a0, a1);
        sts_a(tiles + sA1, a2, a3);
        sts_b(tiles + 8192 + sA0, tiles + 16384 + sA0, b0, b1);
        sts_b(tiles + 8192 + sA1, tiles + 16384 + sA1, b2, b3);
    }
    __syncthreads();

    float acc[2][8][4];
#pragma unroll
    for (int i = 0; i < 2; ++i)
#pragma unroll
        for (int j = 0; j < 8; ++j)
#pragma unroll
            for (int c = 0; c < 4; ++c) acc[i][j][c] = 0.f;

#pragma unroll 1
    for (int kt = 0; kt < KT; ++kt) {
        int b = kt & 1;
        u32 stage = tiles + b * STAGE;

        float4 pa0, pa1, pa2, pa3, pb0, pb1, pb2, pb3;
        bool pf = (kt + 1 < KT);
        if (pf) {
            int k0 = (kt + 1) * BK;
            pa0 = *(const float4*)(aRow + k0);
            pa1 = *(const float4*)(aRow + k0 + 4);
            pa2 = *(const float4*)(aRow + k0 + 8);
            pa3 = *(const float4*)(aRow + k0 + 12);
            pb0 = *(const float4*)(bRow + k0);
            pb1 = *(const float4*)(bRow + k0 + 4);
            pb2 = *(const float4*)(bRow + k0 + 8);
            pb3 = *(const float4*)(bRow + k0 + 12);
        }

#pragma unroll
        for (int ks = 0; ks < 2; ++ks) {
            u32 Ah[2][4];
#pragma unroll
            for (int mi = 0; mi < 2; ++mi) {
                int row = wm * 32 + mi * 16 + (lane & 15);
                int ch = ks * 2 + (lane >> 4);
                LDSM4(Ah[mi], stage + swoff(row, ch));
            }
#pragma unroll
            for (int p = 0; p < 4; ++p) {
                int row = wn * 64 + p * 16 + ((lane >> 4) << 3) + (lane & 7);
                int ch = ks * 2 + ((lane >> 3) & 1);
                u32 off = swoff(row, ch);
                u32 Bh[4], Bl[4];
                LDSM4(Bh, stage + 8192 + off);
                LDSM4(Bl, stage + 16384 + off);
#pragma unroll
                for (int mi = 0; mi < 2; ++mi) {
                    mma16816(acc[mi][2 * p],     Ah[mi], Bh);
                    mma16816(acc[mi][2 * p + 1], Ah[mi], Bh + 2);
                    mma16816(acc[mi][2 * p],     Ah[mi], Bl);
                    mma16816(acc[mi][2 * p + 1], Ah[mi], Bl + 2);
                }
            }
        }

        if (pf) {
            u32 ns = tiles + (b ^ 1) * STAGE;
            sts_a(ns + sA0, pa0, pa1);
            sts_a(ns + sA1, pa2, pa3);
            sts_b(ns + 8192 + sA0, ns + 16384 + sA0, pb0, pb1);
            sts_b(ns + 8192 + sA1, ns + 16384 + sA1, pb2, pb3);
        }
        __syncthreads();
    }

    // epilogue
    int rA = m0 + wm * 32 + (lane >> 2);
    int cA = n0 + wn * 64 + (lane & 3) * 2;
#pragma unroll
    for (int mi = 0; mi < 2; ++mi) {
#pragma unroll
        for (int ni = 0; ni < 8; ++ni) {
            int col = cA + ni * 8;
#pragma unroll
            for (int h = 0; h < 2; ++h) {
                int r = rA + mi * 16 + h * 8;
                if (r >= cnt) continue;
                float v0 = acc[mi][ni][2 * h], v1 = acc[mi][ni][2 * h + 1];
                int slot = base + r;
                if (MODE == 0) {
                    float2 o; o.x = v0; o.y = v1;
                    *(float2*)(g_tmp + (size_t)slot * IDIM + col) = o;
                } else if (MODE == 1) {
                    float2 g = *(const float2*)(g_tmp + (size_t)slot * IDIM + col);
                    float2 o;
                    o.x = g.x / (1.f + __expf(-g.x)) * v0;
                    o.y = g.y / (1.f + __expf(-g.y)) * v1;
                    *(float2*)(g_act + (size_t)slot * IDIM + col) = o;
                } else {
                    float w = g_sw[slot];
                    float* d = outp + (size_t)g_tok[slot] * H + col;
                    atomicAdd(d, w * v0);
                    atomicAdd(d + 1, w * v1);
                }
            }
        }
    }
}

// ---------------- launch ----------------
extern "C" void kernel_launch(void* const* d_in, const int* in_sizes, int n_in,
                              void* d_out, int out_size) {
    const float* x     = (const float*)d_in[0];
    const float* Wgate = (const float*)d_in[1];
    const float* Wg    = (const float*)d_in[2];
    const float* Wu    = (const float*)d_in[3];
    const float* Wd    = (const float*)d_in[4];
    float* out = (float*)d_out;

    cudaFuncSetAttribute(gemm_kernel<0>, cudaFuncAttributeMaxDynamicSharedMemorySize, SMEMSZ);
    cudaFuncSetAttribute(gemm_kernel<1>, cudaFuncAttributeMaxDynamicSharedMemorySize, SMEMSZ);
    cudaFuncSetAttribute(gemm_kernel<2>, cudaFuncAttributeMaxDynamicSharedMemorySize, SMEMSZ);

    cudaMemsetAsync(out, 0, (size_t)out_size * sizeof(float));
    reset_kernel<<<1, 32>>>();
    router_kernel<<<T, 128>>>(x, Wgate);
    finalize_kernel<<<1, 32>>>(out, out_size);
    assign_kernel<<<(T + 255) / 256, 256>>>();

    dim3 g1(T / BM, IDIM / BN, NE);   // (32, 44, 8)
    gemm_kernel<0><<<g1, 256, SMEMSZ>>>(x, Wg, out);
    gemm_kernel<1><<<g1, 256, SMEMSZ>>>(x, Wu, out);

    dim3 g2(T / BM, H / BN, NE);      // (32, 32, 8)
    gemm_kernel<2><<<g2, 256, SMEMSZ>>>(x, Wd, out);
}